// round 5
// baseline (speedup 1.0000x reference)
#include <cuda_runtime.h>
#include <cuda_bf16.h>
#include <float.h>

// PlanPredCollisionLoss: B=128, A=1024, M=6, T=16
// inputs: [0] ego_plan [B,T,2] f32
//         [1] agent_fut_preds [B,A,M,T,2] f32
//         [2] agent_score_preds [B,A,M] f32
//         [3] ego_plan_mask [B,T] f32
// output: scalar f32 mean loss

#define BB 128
#define AA 1024
#define MM 6
#define TT 16
#define NWARP 32   /* 1024 threads / 32 */

#define AGENT_THRESH 0.5f
#define X_DIS_THRESH 1.5f
#define Y_DIS_THRESH 3.0f
#define DIS2_THRESH  9.0f   /* DIS_THRESH^2 (avoids sqrt) */

// per-batch partial sums; fully overwritten every launch -> no init pass needed
__device__ float g_partial[BB];

__global__ void __launch_bounds__(1024) ppcl_main_kernel(
    const float* __restrict__ ego,    // [B,T,2]
    const float* __restrict__ fut,    // [B,A,M,T,2]
    const float* __restrict__ sc,     // [B,A,M]
    const float* __restrict__ mask)   // [B,T]
{
    const int b   = blockIdx.x;
    const int tid = threadIdx.x;     // == agent index a
    const int a   = tid;

    __shared__ float s_ego[TT * 2];
    if (tid < TT * 2) s_ego[tid] = ego[b * TT * 2 + tid];

    // argmax over M=6 modes (first-max tiebreak, matching jnp.argmax)
    const float* s = sc + ((size_t)b * AA + a) * MM;
    float smax = s[0];
    int   bm   = 0;
#pragma unroll
    for (int m = 1; m < MM; m++) {
        float v = s[m];
        if (v > smax) { smax = v; bm = m; }
    }
    const bool low = (smax < AGENT_THRESH);

    // best-mode trajectory: 32 contiguous f32 = 8 float4 (one 128B line)
    const float4* traj = reinterpret_cast<const float4*>(
        fut + (((size_t)b * AA + a) * MM + bm) * (TT * 2));

    __syncthreads();

    float xv[TT], yv[TT];
#pragma unroll
    for (int i = 0; i < TT / 2; i++) {
        float4 p = traj[i];
        {
            const int t = 2 * i;
            float dx = s_ego[2 * t]     - p.x;
            float dy = s_ego[2 * t + 1] - p.y;
            float d2 = dx * dx + dy * dy;
            float pen = (d2 > DIS2_THRESH || low) ? 100.0f : 0.0f;
            xv[t] = fabsf(dx) + pen;
            yv[t] = fabsf(dy) + pen;
        }
        {
            const int t = 2 * i + 1;
            float dx = s_ego[2 * t]     - p.z;
            float dy = s_ego[2 * t + 1] - p.w;
            float d2 = dx * dx + dy * dy;
            float pen = (d2 > DIS2_THRESH || low) ? 100.0f : 0.0f;
            xv[t] = fabsf(dx) + pen;
            yv[t] = fabsf(dy) + pen;
        }
    }

    // intra-warp min for each t
#pragma unroll
    for (int t = 0; t < TT; t++) {
#pragma unroll
        for (int off = 16; off > 0; off >>= 1) {
            xv[t] = fminf(xv[t], __shfl_xor_sync(0xFFFFFFFFu, xv[t], off));
            yv[t] = fminf(yv[t], __shfl_xor_sync(0xFFFFFFFFu, yv[t], off));
        }
    }

    // cross-warp: 32 warps publish 16 x-mins + 16 y-mins each
    __shared__ float s_x[NWARP][TT];
    __shared__ float s_y[NWARP][TT];
    __shared__ float s_xmin[TT];
    __shared__ float s_ymin[TT];
    const int warp = tid >> 5;
    const int lane = tid & 31;
    if (lane == 0) {
#pragma unroll
        for (int t = 0; t < TT; t++) { s_x[warp][t] = xv[t]; s_y[warp][t] = yv[t]; }
    }
    __syncthreads();

    if (tid < TT) {
        float mx = s_x[0][tid];
#pragma unroll
        for (int w = 1; w < NWARP; w++) mx = fminf(mx, s_x[w][tid]);
        s_xmin[tid] = mx;
    } else if (tid < 2 * TT) {
        const int t = tid - TT;
        float my = s_y[0][t];
#pragma unroll
        for (int w = 1; w < NWARP; w++) my = fminf(my, s_y[w][t]);
        s_ymin[t] = my;
    }
    __syncthreads();

    // warp 0: per-t loss, masked, summed -> one partial per batch
    if (tid < 32) {
        float sum = 0.0f;
        if (tid < TT) {
            const float xm = s_xmin[tid];
            const float ym = s_ymin[tid];
            const float xl = (xm <= X_DIS_THRESH) ? (X_DIS_THRESH - xm) : 0.0f;
            const float yl = (ym <= Y_DIS_THRESH) ? (Y_DIS_THRESH - ym) : 0.0f;
            sum = (xl + yl) * mask[b * TT + tid];
        }
#pragma unroll
        for (int off = 16; off > 0; off >>= 1)
            sum += __shfl_xor_sync(0xFFFFFFFFu, sum, off);
        if (tid == 0) g_partial[b] = sum;
    }
}

__global__ void __launch_bounds__(128) ppcl_final_kernel(float* __restrict__ out) {
    const int tid = threadIdx.x;
    float v = g_partial[tid];   // BB == blockDim == 128
#pragma unroll
    for (int off = 16; off > 0; off >>= 1)
        v += __shfl_xor_sync(0xFFFFFFFFu, v, off);

    __shared__ float sw[4];
    if ((tid & 31) == 0) sw[tid >> 5] = v;
    __syncthreads();
    if (tid == 0)
        out[0] = (sw[0] + sw[1] + sw[2] + sw[3]) / (float)(BB * TT * 2); // LOSS_WEIGHT=1
}

extern "C" void kernel_launch(void* const* d_in, const int* in_sizes, int n_in,
                              void* d_out, int out_size) {
    const float* ego  = (const float*)d_in[0];
    const float* fut  = (const float*)d_in[1];
    const float* sc   = (const float*)d_in[2];
    const float* mask = (const float*)d_in[3];
    float* out = (float*)d_out;

    ppcl_main_kernel<<<BB, 1024>>>(ego, fut, sc, mask);
    ppcl_final_kernel<<<1, 128>>>(out);
}

// round 7
// speedup vs baseline: 1.4464x; 1.4464x over previous
#include <cuda_runtime.h>
#include <cuda_bf16.h>
#include <float.h>

// PlanPredCollisionLoss: B=128, A=1024, M=6, T=16
// inputs: [0] ego_plan [B,T,2] f32
//         [1] agent_fut_preds [B,A,M,T,2] f32
//         [2] agent_score_preds [B,A,M] f32
//         [3] ego_plan_mask [B,T] f32
// output: scalar f32 mean loss

#define BB 128
#define AA 1024
#define MM 6
#define TT 16
#define NWARP 32          /* 1024 threads */
#define AGRP  64          /* agent groups in phase 2 (1024/16) */
#define AITER 16          /* agents per thread in phase 2 (1024/64) */

#define AGENT_THRESH 0.5f
#define X_DIS_THRESH 1.5f
#define Y_DIS_THRESH 3.0f
#define DIS2_THRESH  9.0f   /* DIS_THRESH^2, avoids sqrt */

// cross-block state; g_partial fully overwritten each launch, g_count returns
// to 0 at the end of every launch (last block resets it) -> graph-replay safe.
__device__ float    g_partial[BB];
__device__ unsigned g_count;

__global__ void __launch_bounds__(1024) ppcl_kernel(
    const float* __restrict__ ego,    // [B,T,2]
    const float* __restrict__ fut,    // [B,A,M,T,2]
    const float* __restrict__ sc,     // [B,A,M]
    const float* __restrict__ mask,   // [B,T]
    float* __restrict__ out)
{
    const int b    = blockIdx.x;
    const int tid  = threadIdx.x;
    const int warp = tid >> 5;
    const int lane = tid & 31;

    __shared__ float s_ego[TT * 2];
    __shared__ int   s_off[AA];           // packed: (elem_offset<<1)|low
    __shared__ float s_rx[NWARP][TT];
    __shared__ float s_ry[NWARP][TT];

    if (tid < TT * 2) s_ego[tid] = ego[b * TT * 2 + tid];

    // ---------------- phase 1: thread = agent; argmax over M=6 ----------------
    {
        const int a = tid;
        const float2* s2 = reinterpret_cast<const float2*>(
            sc + ((size_t)b * AA + a) * MM);          // 24B stride, 8B aligned
        float2 p0 = s2[0], p1 = s2[1], p2 = s2[2];
        float smax = p0.x; int bm = 0;
        if (p0.y > smax) { smax = p0.y; bm = 1; }
        if (p1.x > smax) { smax = p1.x; bm = 2; }
        if (p1.y > smax) { smax = p1.y; bm = 3; }
        if (p2.x > smax) { smax = p2.x; bm = 4; }
        if (p2.y > smax) { smax = p2.y; bm = 5; }
        const int low = (smax < AGENT_THRESH) ? 1 : 0;
        const int off_elems = (a * MM + bm) * (TT * 2);   // < 2^18
        s_off[a] = (off_elems << 1) | low;
    }
    __syncthreads();

    // ------------- phase 2: thread = (agent_group, t); serial min over 16 agents -------------
    const int t  = tid & 15;          // timestep
    const int ag = tid >> 4;          // agent group 0..63  (= warp*2 + (lane>>4))
    const float egx = s_ego[2 * t];
    const float egy = s_ego[2 * t + 1];
    const float* fut_b = fut + (size_t)b * AA * MM * (TT * 2);

    float xm = FLT_MAX, ym = FLT_MAX;
#pragma unroll
    for (int i = 0; i < AITER; i++) {
        const int a = i * AGRP + ag;
        const int packed = s_off[a];
        const float2 p = *reinterpret_cast<const float2*>(
            fut_b + (packed >> 1) + 2 * t);
        const float dx = egx - p.x;
        const float dy = egy - p.y;
        const float d2 = dx * dx + dy * dy;
        const float pen = (d2 > DIS2_THRESH || (packed & 1)) ? 100.0f : 0.0f;
        xm = fminf(xm, fabsf(dx) + pen);
        ym = fminf(ym, fabsf(dy) + pen);
    }

    // combine the two half-warps (same t, different agent group)
    xm = fminf(xm, __shfl_xor_sync(0xFFFFFFFFu, xm, 16));
    ym = fminf(ym, __shfl_xor_sync(0xFFFFFFFFu, ym, 16));
    if (lane < 16) { s_rx[warp][lane] = xm; s_ry[warp][lane] = ym; }
    __syncthreads();

    // ------------- block tail: warp 0 reduces 32 warps, applies loss+mask -------------
    if (tid < 16) {
        float mx = s_rx[0][tid];
        float my = s_ry[0][tid];
#pragma unroll
        for (int w = 1; w < NWARP; w++) {
            mx = fminf(mx, s_rx[w][tid]);
            my = fminf(my, s_ry[w][tid]);
        }
        const float xl = (mx <= X_DIS_THRESH) ? (X_DIS_THRESH - mx) : 0.0f;
        const float yl = (my <= Y_DIS_THRESH) ? (Y_DIS_THRESH - my) : 0.0f;
        float v = (xl + yl) * mask[b * TT + tid];
#pragma unroll
        for (int off = 8; off > 0; off >>= 1)
            v += __shfl_xor_sync(0x0000FFFFu, v, off, 16);

        if (tid == 0) {
            g_partial[b] = v;
            __threadfence();
            const unsigned old = atomicAdd(&g_count, 1u);
            if (old == BB - 1) {
                // last block: deterministic serial sum of 128 partials
                const volatile float* gp = g_partial;
                float tot = 0.0f;
#pragma unroll
                for (int i = 0; i < BB; i++) tot += gp[i];
                out[0] = tot * (1.0f / (float)(BB * TT * 2));  // LOSS_WEIGHT=1
                g_count = 0;                                    // reset for next replay
                __threadfence();
            }
        }
    }
}

extern "C" void kernel_launch(void* const* d_in, const int* in_sizes, int n_in,
                              void* d_out, int out_size) {
    const float* ego  = (const float*)d_in[0];
    const float* fut  = (const float*)d_in[1];
    const float* sc   = (const float*)d_in[2];
    const float* mask = (const float*)d_in[3];
    float* out = (float*)d_out;

    ppcl_kernel<<<BB, 1024>>>(ego, fut, sc, mask, out);
}